// round 6
// baseline (speedup 1.0000x reference)
#include <cuda_runtime.h>
#include <cuda_bf16.h>
#include <cstdint>

// B=16, T=4096 -> N=65536 tokens, D=64, K=1024
#define D 64
#define K 1024
#define BM 512          // tokens per CTA
#define BK 64           // codes staged per chunk
#define NC (K / BK)     // 16 chunks
#define THREADS 256     // tx=8 code-groups (8 codes), ty=32 token-groups (16 tokens)

typedef unsigned long long ull;

__device__ float g_embedT[K * D];  // [k][d] for the gather epilogue
__device__ float g_h[K];           // 0.5 * ||e_k||^2

__device__ __forceinline__ ull ffma2(ull a, ull b, ull c) {
    ull d_;
    asm("fma.rn.f32x2 %0, %1, %2, %3;" : "=l"(d_) : "l"(a), "l"(b), "l"(c));
    return d_;
}
__device__ __forceinline__ ull dup_f32(float x) {
    ull r;
    asm("mov.b64 %0, {%1, %1};" : "=l"(r) : "f"(x));
    return r;
}
__device__ __forceinline__ float2 unpack2(ull a) {
    float2 u;
    asm("mov.b64 {%0, %1}, %2;" : "=f"(u.x), "=f"(u.y) : "l"(a));
    return u;
}
__device__ __forceinline__ void cp16(uint32_t s, const void* g) {
    asm volatile("cp.async.cg.shared.global [%0], [%1], 16;" :: "r"(s), "l"(g));
}

// ------------- prep: transpose codebook + half norms -------------
__global__ void vq_prep(const float* __restrict__ embed) {
    int i = blockIdx.x * blockDim.x + threadIdx.x;
    if (i < D * K) {
        int k = i >> 6;
        int d = i & 63;
        g_embedT[i] = embed[d * K + k];
    }
    if (i < K) {
        float s = 0.f;
        #pragma unroll
        for (int d = 0; d < D; d++) {
            float v = embed[d * K + i];
            s = fmaf(v, v, s);
        }
        g_h[i] = 0.5f * s;
    }
}

// ------------- main: fused distance GEMM + argmin + gather -------------
__global__ __launch_bounds__(THREADS, 1)
void vq_main(const float* __restrict__ input,
             const float* __restrict__ embed,
             float* __restrict__ q_out,
             float* __restrict__ diff_out,
             float* __restrict__ ind_out) {
    extern __shared__ char smem_raw[];
    float* xs = (float*)smem_raw;                      // [D][BM] transposed x  (128 KB)
    float* es = xs + D * BM;                           // [2][D][BK]            (32 KB)
    float* hs = es + 2 * D * BK;                       // [K]                   (4 KB)
    int*   best_sm = (int*)(hs + K);                   // [BM]                  (2 KB)

    const int tid = threadIdx.x;
    const int tx  = tid & 7;    // 8 code-groups * 8 codes -> BK=64
    const int ty  = tid >> 3;   // 32 token-groups * 16 tokens -> BM=512
    const int n0  = blockIdx.x * BM;

    // ---- prologue: x tile, coalesced read -> transposed shared [d][token] ----
    const float4* in4 = reinterpret_cast<const float4*>(input + (size_t)n0 * D);
    #pragma unroll
    for (int t = tid; t < BM * D / 4; t += THREADS) {
        float4 v = in4[t];
        int row = t >> 4;              // token in tile (0..511)
        int c   = (t & 15) << 2;       // starting d
        xs[(c + 0) * BM + row] = v.x;
        xs[(c + 1) * BM + row] = v.y;
        xs[(c + 2) * BM + row] = v.z;
        xs[(c + 3) * BM + row] = v.w;
    }
    #pragma unroll
    for (int t = tid; t < K; t += THREADS) hs[t] = g_h[t];

    uint32_t es_s = (uint32_t)__cvta_generic_to_shared(es);

    // ---- prefetch chunk 0: D*BK floats = 16KB = 1024 x 16B ----
    #pragma unroll
    for (int i = 0; i < 4; i++) {
        int idx = i * THREADS + tid;
        int d = idx >> 4, c4 = (idx & 15) << 2;
        cp16(es_s + (uint32_t)(d * BK + c4) * 4, embed + (size_t)d * K + c4);
    }
    asm volatile("cp.async.commit_group;");

    float best_s[16];
    int   best_i[16];
    #pragma unroll
    for (int i = 0; i < 16; i++) { best_s[i] = 3.4e38f; best_i[i] = 0; }

    // 8 token-pairs per thread, stride BM/2 = 256 ull per d
    const ull* xrow = (const ull*)xs + ty * 8;

    for (int ck = 0; ck < NC; ck++) {
        asm volatile("cp.async.wait_group 0;");
        __syncthreads();   // chunk ck visible; all warps done with the other buffer

        if (ck + 1 < NC) {
            int kb2 = (ck + 1) * BK;
            uint32_t dst = es_s + (uint32_t)(((ck + 1) & 1) * D * BK) * 4;
            #pragma unroll
            for (int i = 0; i < 4; i++) {
                int idx = i * THREADS + tid;
                int d = idx >> 4, c4 = (idx & 15) << 2;
                cp16(dst + (uint32_t)(d * BK + c4) * 4,
                     embed + (size_t)d * K + kb2 + c4);
            }
            asm volatile("cp.async.commit_group;");
        }

        const float* erow = es + (ck & 1) * D * BK + tx * 8;

        ull acc[8][8];   // [code][token-pair]  = 128 regs
        #pragma unroll
        for (int c = 0; c < 8; c++)
            #pragma unroll
            for (int p = 0; p < 8; p++) acc[c][p] = 0ULL;

        #pragma unroll 2
        for (int d = 0; d < D; d++) {
            // x: 4 conflict-free LDS.128 (4 distinct addrs per 8-lane phase)
            ulonglong2 x01 = *(const ulonglong2*)(xrow + d * (BM / 2) + 0);
            ulonglong2 x23 = *(const ulonglong2*)(xrow + d * (BM / 2) + 2);
            ulonglong2 x45 = *(const ulonglong2*)(xrow + d * (BM / 2) + 4);
            ulonglong2 x67 = *(const ulonglong2*)(xrow + d * (BM / 2) + 6);
            ull xv[8] = {x01.x, x01.y, x23.x, x23.y, x45.x, x45.y, x67.x, x67.y};

            // e: 8 scalar LDS.32 (contiguous 32B per 8-lane phase) + reg dup
            ull ev[8];
            #pragma unroll
            for (int c = 0; c < 8; c++) ev[c] = dup_f32(erow[d * BK + c]);

            #pragma unroll
            for (int c = 0; c < 8; c++) {
                #pragma unroll
                for (int p = 0; p < 8; p++) {
                    acc[c][p] = ffma2(xv[p], ev[c], acc[c][p]);
                }
            }
        }

        // ---- scores + running argmin (ascending k keeps lowest-index tie) ----
        int kb = ck * BK;
        #pragma unroll
        for (int c = 0; c < 8; c++) {
            int k0 = kb + tx * 8 + c;
            float hv = hs[k0];
            #pragma unroll
            for (int p = 0; p < 8; p++) {
                float2 pr = unpack2(acc[c][p]);
                float s0 = hv - pr.x;
                float s1 = hv - pr.y;
                if (s0 < best_s[2 * p])     { best_s[2 * p]     = s0; best_i[2 * p]     = k0; }
                if (s1 < best_s[2 * p + 1]) { best_s[2 * p + 1] = s1; best_i[2 * p + 1] = k0; }
            }
        }
    }

    // ---- reduce over the 8 tx lanes (xor 4,2,1 stays inside each 8-lane group) ----
    #pragma unroll
    for (int j = 0; j < 16; j++) {
        float s = best_s[j];
        int   bi = best_i[j];
        #pragma unroll
        for (int m = 4; m >= 1; m >>= 1) {
            float so = __shfl_xor_sync(0xffffffffu, s, m);
            int   io = __shfl_xor_sync(0xffffffffu, bi, m);
            if (so < s || (so == s && io < bi)) { s = so; bi = io; }
        }
        if (tx == 0) {
            int row = ty * 16 + j;
            best_sm[row] = bi;
            if (ind_out) ind_out[n0 + row] = (float)bi;
        }
    }
    __syncthreads();

    // ---- gather quantize + diff; x re-read from global (coalesced) ----
    #pragma unroll
    for (int t = tid; t < BM * D / 4; t += THREADS) {
        int row = t >> 4;
        int c   = (t & 15) << 2;
        int kq  = best_sm[row];
        float4 q = *(const float4*)(g_embedT + kq * D + c);
        float4 x = in4[t];
        size_t o = (size_t)(n0 + row) * D + c;
        *reinterpret_cast<float4*>(&q_out[o]) = q;
        if (diff_out) {
            float4 df;
            df.x = (q.x - x.x) * (q.x - x.x);
            df.y = (q.y - x.y) * (q.y - x.y);
            df.z = (q.z - x.z) * (q.z - x.z);
            df.w = (q.w - x.w) * (q.w - x.w);
            *reinterpret_cast<float4*>(&diff_out[o]) = df;
        }
    }
}

#define SMEM_BYTES ((size_t)D * BM * 4 + (size_t)2 * D * BK * 4 + K * 4 + BM * 4)

extern "C" void kernel_launch(void* const* d_in, const int* in_sizes, int n_in,
                              void* d_out, int out_size) {
    const float* input = (const float*)d_in[0];   // [B,T,D] fp32
    const float* embed = (const float*)d_in[1];   // [D,K]   fp32

    const int N = in_sizes[0] / D;
    const long nd = (long)N * D;

    float* out = (float*)d_out;
    float* q_out    = out;
    float* diff_out = nullptr;
    float* ind_out  = nullptr;
    if ((long)out_size >= 2 * nd + N) { diff_out = out + nd; ind_out = out + 2 * nd; }
    else if ((long)out_size >= 2 * nd) { diff_out = out + nd; }

    cudaFuncSetAttribute(vq_main, cudaFuncAttributeMaxDynamicSharedMemorySize, (int)SMEM_BYTES);

    vq_prep<<<(D * K + 255) / 256, 256>>>(embed);
    vq_main<<<N / BM, THREADS, SMEM_BYTES>>>(input, embed, q_out, diff_out, ind_out);
}

// round 8
// speedup vs baseline: 1.6132x; 1.6132x over previous
#include <cuda_runtime.h>
#include <cuda_bf16.h>
#include <cstdint>

// B=16, T=4096 -> N=65536 tokens, D=64, K=1024
#define D 64
#define K 1024
#define BMT 128          // tokens per CTA
#define CHN 128          // codes per chunk
#define NCHUNK (K / CHN) // 8
#define THREADS 256      // 8 warps: 4 (M) x 2 (N)

#define TILE_STRIDE 144              // bytes per 64-bf16 row (128 + 16 pad, ldmatrix conflict-free)
#define SPLIT_BYTES (128 * TILE_STRIDE)   // 18432 per 128-row split tile

#define OFF_H    0                        // K floats (4 KB)
#define OFF_SS   4096                     // s_score[128]
#define OFF_SI   4608                     // s_idx[128]
#define OFF_A    5120                     // 3 A split tiles
#define OFF_B    (OFF_A + 3 * SPLIT_BYTES)        // 2 buf x 3 split tiles
#define SMEM_TOTAL (OFF_B + 6 * SPLIT_BYTES)      // 171008 B

__device__ float          g_embedT[K * D];   // [k][d] fp32 for gather
__device__ float          g_h[K];            // 0.5 * ||e_k||^2
__device__ __nv_bfloat16  g_e0[K * D];       // [k][d] bf16 split hi
__device__ __nv_bfloat16  g_e1[K * D];       // mid
__device__ __nv_bfloat16  g_e2[K * D];       // lo

__device__ __forceinline__ void cp16(uint32_t s, const void* g) {
    asm volatile("cp.async.cg.shared.global [%0], [%1], 16;" :: "r"(s), "l"(g));
}
#define CP_COMMIT()  asm volatile("cp.async.commit_group;")
#define CP_WAIT0()   asm volatile("cp.async.wait_group 0;")

__device__ __forceinline__ void ldsm4(uint32_t r[4], uint32_t addr) {
    asm volatile("ldmatrix.sync.aligned.m8n8.x4.shared.b16 {%0,%1,%2,%3}, [%4];"
        : "=r"(r[0]), "=r"(r[1]), "=r"(r[2]), "=r"(r[3]) : "r"(addr));
}
__device__ __forceinline__ void mma16816(float c[4], const uint32_t a[4],
                                         uint32_t b0, uint32_t b1) {
    asm volatile("mma.sync.aligned.m16n8k16.row.col.f32.bf16.bf16.f32 "
        "{%0,%1,%2,%3}, {%4,%5,%6,%7}, {%8,%9}, {%0,%1,%2,%3};"
        : "+f"(c[0]), "+f"(c[1]), "+f"(c[2]), "+f"(c[3])
        : "r"(a[0]), "r"(a[1]), "r"(a[2]), "r"(a[3]), "r"(b0), "r"(b1));
}

__device__ __forceinline__ uint32_t pack_bf16x2(__nv_bfloat16 lo, __nv_bfloat16 hi) {
    return (uint32_t)__bfloat16_as_ushort(lo) | ((uint32_t)__bfloat16_as_ushort(hi) << 16);
}

// ------------- prep: splits [k][d], transpose, norms -------------
__global__ void vq_prep(const float* __restrict__ embed) {
    int i = blockIdx.x * blockDim.x + threadIdx.x;
    if (i < K * D) {
        int k = i >> 6;
        int d = i & 63;
        float v = embed[d * K + k];
        g_embedT[i] = v;
        __nv_bfloat16 b0 = __float2bfloat16(v);
        float r = v - __bfloat162float(b0);
        __nv_bfloat16 b1 = __float2bfloat16(r);
        float r2 = r - __bfloat162float(b1);
        g_e0[i] = b0; g_e1[i] = b1; g_e2[i] = __float2bfloat16(r2);
    }
    if (i < K) {
        float s = 0.f;
        #pragma unroll
        for (int d = 0; d < D; d++) {
            float v = embed[d * K + i];
            s = fmaf(v, v, s);
        }
        g_h[i] = 0.5f * s;
    }
}

// ------------- main: split-bf16 HMMA distance GEMM + argmin + gather -------------
__global__ __launch_bounds__(THREADS, 1)
void vq_main(const float* __restrict__ input,
             float* __restrict__ q_out,
             float* __restrict__ diff_out,
             float* __restrict__ ind_out) {
    extern __shared__ char smem[];
    const uint32_t sb = (uint32_t)__cvta_generic_to_shared(smem);
    float* hs   = (float*)(smem + OFF_H);
    float* s_sc = (float*)(smem + OFF_SS);
    int*   s_ix = (int*)(smem + OFF_SI);

    const int tid  = threadIdx.x;
    const int wid  = tid >> 5;
    const int lane = tid & 31;
    const int wm   = wid >> 1;   // 0..3 : token rows 32*wm
    const int wn   = wid & 1;    // 0..1 : code cols 64*wn
    const int n0   = blockIdx.x * BMT;

    // ---- prologue: x [128][64] fp32 -> 3 bf16 split tiles in smem ----
    const float4* in4 = reinterpret_cast<const float4*>(input + (size_t)n0 * D);
    #pragma unroll
    for (int t = 0; t < 8; t++) {
        int idx = t * THREADS + tid;       // 0..2047 float4
        float4 v = in4[idx];
        int row = idx >> 4;                // token 0..127
        int c   = (idx & 15) << 2;         // starting d
        float vv[4] = {v.x, v.y, v.z, v.w};
        __nv_bfloat16 s0[4], s1[4], s2[4];
        #pragma unroll
        for (int q = 0; q < 4; q++) {
            float a = vv[q];
            s0[q] = __float2bfloat16(a);
            float r = a - __bfloat162float(s0[q]);
            s1[q] = __float2bfloat16(r);
            s2[q] = __float2bfloat16(r - __bfloat162float(s1[q]));
        }
        char* base = smem + OFF_A + row * TILE_STRIDE + c * 2;
        *(uint32_t*)(base + 0 * SPLIT_BYTES)     = pack_bf16x2(s0[0], s0[1]);
        *(uint32_t*)(base + 0 * SPLIT_BYTES + 4) = pack_bf16x2(s0[2], s0[3]);
        *(uint32_t*)(base + 1 * SPLIT_BYTES)     = pack_bf16x2(s1[0], s1[1]);
        *(uint32_t*)(base + 1 * SPLIT_BYTES + 4) = pack_bf16x2(s1[2], s1[3]);
        *(uint32_t*)(base + 2 * SPLIT_BYTES)     = pack_bf16x2(s2[0], s2[1]);
        *(uint32_t*)(base + 2 * SPLIT_BYTES + 4) = pack_bf16x2(s2[2], s2[3]);
    }
    #pragma unroll
    for (int t = tid; t < K; t += THREADS) hs[t] = g_h[t];

    // ---- prefetch B chunk 0: 3 splits x 128 rows x 8 granules ----
    const __nv_bfloat16* gsrc[3] = {g_e0, g_e1, g_e2};
    #pragma unroll
    for (int i = 0; i < 12; i++) {
        int idx = i * THREADS + tid;       // < 3072
        int sp = idx >> 10, rem = idx & 1023;
        int row = rem >> 3, g = rem & 7;
        cp16(sb + OFF_B + sp * SPLIT_BYTES + row * TILE_STRIDE + g * 16,
             gsrc[sp] + (size_t)row * 64 + g * 8);
    }
    CP_COMMIT();

    // per-thread best over 4 row-slots (i*2+half), row = wm*32+i*16+half*8+lane/4
    float bs[4];
    int   bi[4];
    #pragma unroll
    for (int s = 0; s < 4; s++) { bs[s] = 3.4e38f; bi[s] = 0; }

    // lane-derived fragment address pieces
    const int l7  = lane & 7;
    const int aRowSel = ((lane >> 3) & 1) << 3;   // A: mat&1 -> +8 rows
    const int aKSel   = (lane >> 4) << 4;         // A: mat>>1 -> +16 bytes (8 bf16 k)
    const int bRowSel = (lane >> 4) << 3;         // B: mat>>1 -> +8 rows
    const int bKSel   = ((lane >> 3) & 1) << 4;   // B: mat&1 -> +16 bytes

    for (int c = 0; c < NCHUNK; c++) {
        CP_WAIT0();
        __syncthreads();   // chunk c staged; all warps done with the other buffer

        if (c + 1 < NCHUNK) {
            int kb = (c + 1) * CHN;
            uint32_t bufo = (uint32_t)(OFF_B + ((c + 1) & 1) * 3 * SPLIT_BYTES);
            #pragma unroll
            for (int i = 0; i < 12; i++) {
                int idx = i * THREADS + tid;
                int sp = idx >> 10, rem = idx & 1023;
                int row = rem >> 3, g = rem & 7;
                cp16(sb + bufo + sp * SPLIT_BYTES + row * TILE_STRIDE + g * 16,
                     gsrc[sp] + (size_t)(kb + row) * 64 + g * 8);
            }
            CP_COMMIT();
        }

        const uint32_t bbase = sb + (uint32_t)(OFF_B + (c & 1) * 3 * SPLIT_BYTES);

        float acc[2][8][4];
        #pragma unroll
        for (int i = 0; i < 2; i++)
            #pragma unroll
            for (int j = 0; j < 8; j++)
                #pragma unroll
                for (int q = 0; q < 4; q++) acc[i][j][q] = 0.f;

        const int bcnt[3] = {3, 2, 1};   // A0x{B0,B1,B2}, A1x{B0,B1}, A2x{B0}
        #pragma unroll
        for (int s = 0; s < 3; s++) {
            uint32_t af[4][2][4];
            #pragma unroll
            for (int ks = 0; ks < 4; ks++)
                #pragma unroll
                for (int i = 0; i < 2; i++) {
                    uint32_t addr = sb + (uint32_t)(OFF_A + s * SPLIT_BYTES)
                        + (uint32_t)((wm * 32 + i * 16 + aRowSel + l7) * TILE_STRIDE)
                        + (uint32_t)(ks * 32 + aKSel);
                    ldsm4(af[ks][i], addr);
                }
            #pragma unroll
            for (int t = 0; t < 3; t++) {
                if (t < bcnt[s]) {
                    #pragma unroll
                    for (int ks = 0; ks < 4; ks++) {
                        uint32_t bf4[4][4];
                        #pragma unroll
                        for (int jj = 0; jj < 4; jj++) {
                            uint32_t addr = bbase + (uint32_t)(t * SPLIT_BYTES)
                                + (uint32_t)((wn * 64 + jj * 16 + bRowSel + l7) * TILE_STRIDE)
                                + (uint32_t)(ks * 32 + bKSel);
                            ldsm4(bf4[jj], addr);
                        }
                        #pragma unroll
                        for (int i = 0; i < 2; i++)
                            #pragma unroll
                            for (int jj = 0; jj < 4; jj++) {
                                mma16816(acc[i][jj * 2 + 0], af[ks][i], bf4[jj][0], bf4[jj][1]);
                                mma16816(acc[i][jj * 2 + 1], af[ks][i], bf4[jj][2], bf4[jj][3]);
                            }
                    }
                }
            }
        }

        // ---- scores + running argmin (lexicographic -> reference tie-break) ----
        #pragma unroll
        for (int i = 0; i < 2; i++)
            #pragma unroll
            for (int j = 0; j < 8; j++) {
                int k0 = c * CHN + wn * 64 + j * 8 + (lane & 3) * 2;
                float h0 = hs[k0], h1 = hs[k0 + 1];
                float s00 = h0 - acc[i][j][0];   // row lane/4,     col k0
                float s01 = h1 - acc[i][j][1];   // row lane/4,     col k0+1
                float s10 = h0 - acc[i][j][2];   // row lane/4 + 8, col k0
                float s11 = h1 - acc[i][j][3];
                int sl0 = i * 2, sl1 = i * 2 + 1;
                if (s00 < bs[sl0] || (s00 == bs[sl0] && k0     < bi[sl0])) { bs[sl0] = s00; bi[sl0] = k0; }
                if (s01 < bs[sl0] || (s01 == bs[sl0] && k0 + 1 < bi[sl0])) { bs[sl0] = s01; bi[sl0] = k0 + 1; }
                if (s10 < bs[sl1] || (s10 == bs[sl1] && k0     < bi[sl1])) { bs[sl1] = s10; bi[sl1] = k0; }
                if (s11 < bs[sl1] || (s11 == bs[sl1] && k0 + 1 < bi[sl1])) { bs[sl1] = s11; bi[sl1] = k0 + 1; }
            }
        __syncthreads();   // B buffer free for next prefetch
    }

    // ---- reduce across the 4 lanes sharing a row (xor 1, 2) ----
    #pragma unroll
    for (int sl = 0; sl < 4; sl++) {
        float s = bs[sl]; int ix = bi[sl];
        #pragma unroll
        for (int m = 1; m <= 2; m <<= 1) {
            float so = __shfl_xor_sync(0xffffffffu, s, m);
            int   io = __shfl_xor_sync(0xffffffffu, ix, m);
            if (so < s || (so == s && io < ix)) { s = so; ix = io; }
        }
        bs[sl] = s; bi[sl] = ix;
    }
    if (wn == 0 && (lane & 3) == 0) {
        #pragma unroll
        for (int sl = 0; sl < 4; sl++) {
            int row = wm * 32 + (sl >> 1) * 16 + (sl & 1) * 8 + (lane >> 2);
            s_sc[row] = bs[sl]; s_ix[row] = bi[sl];
        }
    }
    __syncthreads();
    if (wn == 1 && (lane & 3) == 0) {
        #pragma unroll
        for (int sl = 0; sl < 4; sl++) {
            int row = wm * 32 + (sl >> 1) * 16 + (sl & 1) * 8 + (lane >> 2);
            float cur = s_sc[row]; int ci = s_ix[row];
            if (bs[sl] < cur || (bs[sl] == cur && bi[sl] < ci)) {
                s_sc[row] = bs[sl]; s_ix[row] = bi[sl];
            }
        }
    }
    __syncthreads();
    if (ind_out && tid < BMT) ind_out[n0 + tid] = (float)s_ix[tid];

    // ---- gather quantize + diff (coalesced float4) ----
    #pragma unroll
    for (int t = 0; t < 8; t++) {
        int idx = t * THREADS + tid;
        int row = idx >> 4;
        int cc  = (idx & 15) << 2;
        int kq  = s_ix[row];
        float4 q = *(const float4*)(g_embedT + kq * D + cc);
        float4 x = in4[idx];
        size_t o = (size_t)(n0 + row) * D + cc;
        *reinterpret_cast<float4*>(&q_out[o]) = q;
        if (diff_out) {
            float4 df;
            df.x = (q.x - x.x) * (q.x - x.x);
            df.y = (q.y - x.y) * (q.y - x.y);
            df.z = (q.z - x.z) * (q.z - x.z);
            df.w = (q.w - x.w) * (q.w - x.w);
            *reinterpret_cast<float4*>(&diff_out[o]) = df;
        }
    }
}

extern "C" void kernel_launch(void* const* d_in, const int* in_sizes, int n_in,
                              void* d_out, int out_size) {
    const float* input = (const float*)d_in[0];   // [B,T,D] fp32
    const float* embed = (const float*)d_in[1];   // [D,K]   fp32

    const int N = in_sizes[0] / D;
    const long nd = (long)N * D;

    float* out = (float*)d_out;
    float* q_out    = out;
    float* diff_out = nullptr;
    float* ind_out  = nullptr;
    if ((long)out_size >= 2 * nd + N) { diff_out = out + nd; ind_out = out + 2 * nd; }
    else if ((long)out_size >= 2 * nd) { diff_out = out + nd; }

    cudaFuncSetAttribute(vq_main, cudaFuncAttributeMaxDynamicSharedMemorySize, SMEM_TOTAL);

    vq_prep<<<(K * D + 255) / 256, 256>>>(embed);
    vq_main<<<N / BMT, THREADS, SMEM_TOTAL>>>(input, q_out, diff_out, ind_out);
}

// round 9
// speedup vs baseline: 1.7601x; 1.0911x over previous
#include <cuda_runtime.h>
#include <cuda_bf16.h>
#include <cstdint>

// B=16, T=4096 -> N=65536 tokens, D=64, K=1024
#define D 64
#define K 1024
#define BMT 128          // tokens per CTA
#define CHN 128          // codes per chunk
#define NCHUNK (K / CHN) // 8
#define THREADS 512      // 16 warps: 8 (M, 16 rows each) x 2 (N, 64 cols each)

#define TILE_STRIDE 144              // bytes per 64-bf16 row (128 + 16 pad -> ldmatrix conflict-free)
#define SPLIT_BYTES (128 * TILE_STRIDE)   // 18432 per 128-row split tile

#define OFF_H    0                        // K floats (4 KB)
#define OFF_SS   4096                     // s_score[128]
#define OFF_SI   4608                     // s_idx[128]
#define OFF_A    5120                     // 3 A split tiles
#define OFF_B    (OFF_A + 3 * SPLIT_BYTES)        // 2 buf x 3 split tiles
#define SMEM_TOTAL (OFF_B + 6 * SPLIT_BYTES)      // 171008 B

__device__ float          g_embedT[K * D];   // [k][d] fp32 for gather
__device__ float          g_h[K];            // 0.5 * ||e_k||^2
__device__ __nv_bfloat16  g_e0[K * D];       // [k][d] bf16 split hi
__device__ __nv_bfloat16  g_e1[K * D];       // mid
__device__ __nv_bfloat16  g_e2[K * D];       // lo

__device__ __forceinline__ void cp16(uint32_t s, const void* g) {
    asm volatile("cp.async.cg.shared.global [%0], [%1], 16;" :: "r"(s), "l"(g));
}
#define CP_COMMIT()  asm volatile("cp.async.commit_group;")
#define CP_WAIT0()   asm volatile("cp.async.wait_group 0;")

__device__ __forceinline__ void ldsm4(uint32_t r[4], uint32_t addr) {
    asm volatile("ldmatrix.sync.aligned.m8n8.x4.shared.b16 {%0,%1,%2,%3}, [%4];"
        : "=r"(r[0]), "=r"(r[1]), "=r"(r[2]), "=r"(r[3]) : "r"(addr));
}
__device__ __forceinline__ void mma16816(float c[4], const uint32_t a[4],
                                         uint32_t b0, uint32_t b1) {
    asm volatile("mma.sync.aligned.m16n8k16.row.col.f32.bf16.bf16.f32 "
        "{%0,%1,%2,%3}, {%4,%5,%6,%7}, {%8,%9}, {%0,%1,%2,%3};"
        : "+f"(c[0]), "+f"(c[1]), "+f"(c[2]), "+f"(c[3])
        : "r"(a[0]), "r"(a[1]), "r"(a[2]), "r"(a[3]), "r"(b0), "r"(b1));
}
__device__ __forceinline__ uint32_t pack_bf16x2(__nv_bfloat16 lo, __nv_bfloat16 hi) {
    return (uint32_t)__bfloat16_as_ushort(lo) | ((uint32_t)__bfloat16_as_ushort(hi) << 16);
}

// ------------- prep: splits [k][d], transpose, norms -------------
__global__ void vq_prep(const float* __restrict__ embed) {
    int i = blockIdx.x * blockDim.x + threadIdx.x;
    if (i < K * D) {
        int k = i >> 6;
        int d = i & 63;
        float v = embed[d * K + k];
        g_embedT[i] = v;
        __nv_bfloat16 b0 = __float2bfloat16(v);
        float r = v - __bfloat162float(b0);
        __nv_bfloat16 b1 = __float2bfloat16(r);
        float r2 = r - __bfloat162float(b1);
        g_e0[i] = b0; g_e1[i] = b1; g_e2[i] = __float2bfloat16(r2);
    }
    if (i < K) {
        float s = 0.f;
        #pragma unroll
        for (int d = 0; d < D; d++) {
            float v = embed[d * K + i];
            s = fmaf(v, v, s);
        }
        g_h[i] = 0.5f * s;
    }
}

// ------------- main: split-bf16 HMMA distance GEMM + argmin + gather -------------
__global__ __launch_bounds__(THREADS, 1)
void vq_main(const float* __restrict__ input,
             float* __restrict__ q_out,
             float* __restrict__ diff_out,
             float* __restrict__ ind_out) {
    extern __shared__ char smem[];
    const uint32_t sb = (uint32_t)__cvta_generic_to_shared(smem);
    float* hs   = (float*)(smem + OFF_H);
    float* s_sc = (float*)(smem + OFF_SS);
    int*   s_ix = (int*)(smem + OFF_SI);

    const int tid  = threadIdx.x;
    const int wid  = tid >> 5;
    const int lane = tid & 31;
    const int wm   = wid >> 1;   // 0..7 : token rows 16*wm
    const int wn   = wid & 1;    // 0..1 : code cols 64*wn
    const int n0   = blockIdx.x * BMT;

    // ---- prologue: x [128][64] fp32 -> 3 bf16 split tiles in smem ----
    const float4* in4 = reinterpret_cast<const float4*>(input + (size_t)n0 * D);
    #pragma unroll
    for (int t = 0; t < 4; t++) {
        int idx = t * THREADS + tid;       // 0..2047 float4
        float4 v = in4[idx];
        int row = idx >> 4;                // token 0..127
        int c   = (idx & 15) << 2;         // starting d
        float vv[4] = {v.x, v.y, v.z, v.w};
        __nv_bfloat16 s0[4], s1[4], s2[4];
        #pragma unroll
        for (int q = 0; q < 4; q++) {
            float a = vv[q];
            s0[q] = __float2bfloat16(a);
            float r = a - __bfloat162float(s0[q]);
            s1[q] = __float2bfloat16(r);
            s2[q] = __float2bfloat16(r - __bfloat162float(s1[q]));
        }
        char* base = smem + OFF_A + row * TILE_STRIDE + c * 2;
        *(uint32_t*)(base + 0 * SPLIT_BYTES)     = pack_bf16x2(s0[0], s0[1]);
        *(uint32_t*)(base + 0 * SPLIT_BYTES + 4) = pack_bf16x2(s0[2], s0[3]);
        *(uint32_t*)(base + 1 * SPLIT_BYTES)     = pack_bf16x2(s1[0], s1[1]);
        *(uint32_t*)(base + 1 * SPLIT_BYTES + 4) = pack_bf16x2(s1[2], s1[3]);
        *(uint32_t*)(base + 2 * SPLIT_BYTES)     = pack_bf16x2(s2[0], s2[1]);
        *(uint32_t*)(base + 2 * SPLIT_BYTES + 4) = pack_bf16x2(s2[2], s2[3]);
    }
    #pragma unroll
    for (int t = tid; t < K; t += THREADS) hs[t] = g_h[t];

    // ---- prefetch B chunk 0: 3 splits x 128 rows x 8 granules = 3072 ----
    const __nv_bfloat16* gsrc[3] = {g_e0, g_e1, g_e2};
    #pragma unroll
    for (int i = 0; i < 6; i++) {
        int idx = i * THREADS + tid;
        int sp = idx >> 10, rem = idx & 1023;
        int row = rem >> 3, g = rem & 7;
        cp16(sb + OFF_B + sp * SPLIT_BYTES + row * TILE_STRIDE + g * 16,
             gsrc[sp] + (size_t)row * 64 + g * 8);
    }
    CP_COMMIT();

    __syncthreads();   // A tiles + hs visible

    // lane-derived fragment address pieces
    const int l7      = lane & 7;
    const int aRowSel = ((lane >> 3) & 1) << 3;   // A: mat&1 -> +8 rows
    const int aKSel   = (lane >> 4) << 4;         // A: mat>>1 -> +16 bytes
    const int bRowSel = (lane >> 4) << 3;         // B: mat>>1 -> +8 rows
    const int bKSel   = ((lane >> 3) & 1) << 4;   // B: mat&1 -> +16 bytes

    // ---- A fragments: chunk-invariant, load ONCE into registers ----
    uint32_t afr[3][4][4];    // [split][ks][frag]  = 48 regs
    #pragma unroll
    for (int s = 0; s < 3; s++)
        #pragma unroll
        for (int ks = 0; ks < 4; ks++) {
            uint32_t addr = sb + (uint32_t)(OFF_A + s * SPLIT_BYTES)
                + (uint32_t)((wm * 16 + aRowSel + l7) * TILE_STRIDE)
                + (uint32_t)(ks * 32 + aKSel);
            ldsm4(afr[s][ks], addr);
        }

    // per-thread best over 2 row-slots: row = wm*16 + slot*8 + lane/4
    float bs[2] = {3.4e38f, 3.4e38f};
    int   bi[2] = {0, 0};

    for (int c = 0; c < NCHUNK; c++) {
        CP_WAIT0();
        __syncthreads();   // chunk c staged; all warps done with the other buffer

        if (c + 1 < NCHUNK) {
            int kb = (c + 1) * CHN;
            uint32_t bufo = (uint32_t)(OFF_B + ((c + 1) & 1) * 3 * SPLIT_BYTES);
            #pragma unroll
            for (int i = 0; i < 6; i++) {
                int idx = i * THREADS + tid;
                int sp = idx >> 10, rem = idx & 1023;
                int row = rem >> 3, g = rem & 7;
                cp16(sb + bufo + sp * SPLIT_BYTES + row * TILE_STRIDE + g * 16,
                     gsrc[sp] + (size_t)(kb + row) * 64 + g * 8);
            }
            CP_COMMIT();
        }

        const uint32_t bbase = sb + (uint32_t)(OFF_B + (c & 1) * 3 * SPLIT_BYTES);

        float acc[8][4];
        #pragma unroll
        for (int j = 0; j < 8; j++)
            #pragma unroll
            for (int q = 0; q < 4; q++) acc[j][q] = 0.f;

        // products: (A-split s, B-split t) with s + t <= 2  -> B loaded once per (t, ks)
        #pragma unroll
        for (int t = 0; t < 3; t++) {
            #pragma unroll
            for (int ks = 0; ks < 4; ks++) {
                uint32_t bf[4][4];
                #pragma unroll
                for (int jj = 0; jj < 4; jj++) {
                    uint32_t addr = bbase + (uint32_t)(t * SPLIT_BYTES)
                        + (uint32_t)((wn * 64 + jj * 16 + bRowSel + l7) * TILE_STRIDE)
                        + (uint32_t)(ks * 32 + bKSel);
                    ldsm4(bf[jj], addr);
                }
                #pragma unroll
                for (int s = 0; s < 3; s++) {
                    if (s + t <= 2) {
                        #pragma unroll
                        for (int jj = 0; jj < 4; jj++) {
                            mma16816(acc[jj * 2 + 0], afr[s][ks], bf[jj][0], bf[jj][1]);
                            mma16816(acc[jj * 2 + 1], afr[s][ks], bf[jj][2], bf[jj][3]);
                        }
                    }
                }
            }
        }

        // ---- scores + running argmin (lexicographic -> reference tie-break) ----
        #pragma unroll
        for (int j = 0; j < 8; j++) {
            int k0 = c * CHN + wn * 64 + j * 8 + (lane & 3) * 2;
            float h0 = hs[k0], h1 = hs[k0 + 1];
            float s00 = h0 - acc[j][0];   // row lane/4,     col k0
            float s01 = h1 - acc[j][1];   // row lane/4,     col k0+1
            float s10 = h0 - acc[j][2];   // row lane/4 + 8, col k0
            float s11 = h1 - acc[j][3];
            if (s00 < bs[0] || (s00 == bs[0] && k0     < bi[0])) { bs[0] = s00; bi[0] = k0; }
            if (s01 < bs[0] || (s01 == bs[0] && k0 + 1 < bi[0])) { bs[0] = s01; bi[0] = k0 + 1; }
            if (s10 < bs[1] || (s10 == bs[1] && k0     < bi[1])) { bs[1] = s10; bi[1] = k0; }
            if (s11 < bs[1] || (s11 == bs[1] && k0 + 1 < bi[1])) { bs[1] = s11; bi[1] = k0 + 1; }
        }
        __syncthreads();   // B buffer free for next prefetch
    }

    // ---- reduce across the 4 lanes sharing a row (xor 1, 2) ----
    #pragma unroll
    for (int sl = 0; sl < 2; sl++) {
        float s = bs[sl]; int ix = bi[sl];
        #pragma unroll
        for (int m = 1; m <= 2; m <<= 1) {
            float so = __shfl_xor_sync(0xffffffffu, s, m);
            int   io = __shfl_xor_sync(0xffffffffu, ix, m);
            if (so < s || (so == s && io < ix)) { s = so; ix = io; }
        }
        bs[sl] = s; bi[sl] = ix;
    }
    if (wn == 0 && (lane & 3) == 0) {
        #pragma unroll
        for (int sl = 0; sl < 2; sl++) {
            int row = wm * 16 + sl * 8 + (lane >> 2);
            s_sc[row] = bs[sl]; s_ix[row] = bi[sl];
        }
    }
    __syncthreads();
    if (wn == 1 && (lane & 3) == 0) {
        #pragma unroll
        for (int sl = 0; sl < 2; sl++) {
            int row = wm * 16 + sl * 8 + (lane >> 2);
            float cur = s_sc[row]; int ci = s_ix[row];
            if (bs[sl] < cur || (bs[sl] == cur && bi[sl] < ci)) {
                s_sc[row] = bs[sl]; s_ix[row] = bi[sl];
            }
        }
    }
    __syncthreads();
    if (ind_out && tid < BMT) ind_out[n0 + tid] = (float)s_ix[tid];

    // ---- gather quantize + diff (coalesced float4) ----
    #pragma unroll
    for (int t = 0; t < 4; t++) {
        int idx = t * THREADS + tid;
        int row = idx >> 4;
        int cc  = (idx & 15) << 2;
        int kq  = s_ix[row];
        float4 q = *(const float4*)(g_embedT + kq * D + cc);
        float4 x = in4[idx];
        size_t o = (size_t)(n0 + row) * D + cc;
        *reinterpret_cast<float4*>(&q_out[o]) = q;
        if (diff_out) {
            float4 df;
            df.x = (q.x - x.x) * (q.x - x.x);
            df.y = (q.y - x.y) * (q.y - x.y);
            df.z = (q.z - x.z) * (q.z - x.z);
            df.w = (q.w - x.w) * (q.w - x.w);
            *reinterpret_cast<float4*>(&diff_out[o]) = df;
        }
    }
}

extern "C" void kernel_launch(void* const* d_in, const int* in_sizes, int n_in,
                              void* d_out, int out_size) {
    const float* input = (const float*)d_in[0];   // [B,T,D] fp32
    const float* embed = (const float*)d_in[1];   // [D,K]   fp32

    const int N = in_sizes[0] / D;
    const long nd = (long)N * D;

    float* out = (float*)d_out;
    float* q_out    = out;
    float* diff_out = nullptr;
    float* ind_out  = nullptr;
    if ((long)out_size >= 2 * nd + N) { diff_out = out + nd; ind_out = out + 2 * nd; }
    else if ((long)out_size >= 2 * nd) { diff_out = out + nd; }

    cudaFuncSetAttribute(vq_main, cudaFuncAttributeMaxDynamicSharedMemorySize, SMEM_TOTAL);

    vq_prep<<<(K * D + 255) / 256, 256>>>(embed);
    vq_main<<<N / BMT, THREADS, SMEM_TOTAL>>>(input, q_out, diff_out, ind_out);
}

// round 10
// speedup vs baseline: 1.9201x; 1.0909x over previous
#include <cuda_runtime.h>
#include <cuda_bf16.h>
#include <cstdint>

// B=16, T=4096 -> N=65536 tokens, D=64, K=1024
#define D 64
#define K 1024
#define BMT 128          // tokens per CTA
#define CHN 64           // codes per chunk
#define NCHUNK (K / CHN) // 16
#define THREADS 256      // 8 warps, all M (16 token rows each); each spans all 64 chunk codes

#define TILE_BYTES 16384             // 128 rows x 128 B (bf16 x 64), SW128-swizzled
#define BTILE_BYTES 8192             // 64 rows x 128 B

#define OFF_H    0                   // K floats (4 KB)
#define OFF_SI   4096                // s_idx[128]
#define OFF_A    5120                // 3 A split tiles (48 KB), 1024-aligned
#define OFF_B    (OFF_A + 3 * TILE_BYTES)          // 2 buf x 3 splits x 8 KB
#define SMEM_TOTAL (OFF_B + 6 * BTILE_BYTES)       // 103424 B -> 2 CTAs/SM

#define SWZ(b) ((b) ^ (((b) >> 3) & 0x70))

__device__ float          g_embedT[K * D];   // [k][d] fp32 for gather
__device__ float          g_h[K];            // 0.5 * ||e_k||^2
__device__ __nv_bfloat16  g_e0[K * D];       // [k][d] bf16 split hi
__device__ __nv_bfloat16  g_e1[K * D];       // mid
__device__ __nv_bfloat16  g_e2[K * D];       // lo

__device__ __forceinline__ void cp16(uint32_t s, const void* g) {
    asm volatile("cp.async.cg.shared.global [%0], [%1], 16;" :: "r"(s), "l"(g));
}
#define CP_COMMIT()  asm volatile("cp.async.commit_group;")
#define CP_WAIT0()   asm volatile("cp.async.wait_group 0;")

__device__ __forceinline__ void ldsm4(uint32_t r[4], uint32_t addr) {
    asm volatile("ldmatrix.sync.aligned.m8n8.x4.shared.b16 {%0,%1,%2,%3}, [%4];"
        : "=r"(r[0]), "=r"(r[1]), "=r"(r[2]), "=r"(r[3]) : "r"(addr));
}
__device__ __forceinline__ void mma16816(float c[4], const uint32_t a[4],
                                         uint32_t b0, uint32_t b1) {
    asm volatile("mma.sync.aligned.m16n8k16.row.col.f32.bf16.bf16.f32 "
        "{%0,%1,%2,%3}, {%4,%5,%6,%7}, {%8,%9}, {%0,%1,%2,%3};"
        : "+f"(c[0]), "+f"(c[1]), "+f"(c[2]), "+f"(c[3])
        : "r"(a[0]), "r"(a[1]), "r"(a[2]), "r"(a[3]), "r"(b0), "r"(b1));
}
__device__ __forceinline__ uint32_t pack_bf16x2(__nv_bfloat16 lo, __nv_bfloat16 hi) {
    return (uint32_t)__bfloat16_as_ushort(lo) | ((uint32_t)__bfloat16_as_ushort(hi) << 16);
}

// ------------- prep: splits [k][d], transpose, norms -------------
__global__ void vq_prep(const float* __restrict__ embed) {
    int i = blockIdx.x * blockDim.x + threadIdx.x;
    if (i < K * D) {
        int k = i >> 6;
        int d = i & 63;
        float v = embed[d * K + k];
        g_embedT[i] = v;
        __nv_bfloat16 b0 = __float2bfloat16(v);
        float r = v - __bfloat162float(b0);
        __nv_bfloat16 b1 = __float2bfloat16(r);
        float r2 = r - __bfloat162float(b1);
        g_e0[i] = b0; g_e1[i] = b1; g_e2[i] = __float2bfloat16(r2);
    }
    if (i < K) {
        float s = 0.f;
        #pragma unroll
        for (int d = 0; d < D; d++) {
            float v = embed[d * K + i];
            s = fmaf(v, v, s);
        }
        g_h[i] = 0.5f * s;
    }
}

// ------------- main: split-bf16 HMMA distance GEMM + argmin + gather -------------
__global__ __launch_bounds__(THREADS, 2)
void vq_main(const float* __restrict__ input,
             float* __restrict__ q_out,
             float* __restrict__ diff_out,
             float* __restrict__ ind_out) {
    extern __shared__ char smem[];
    const uint32_t sb = (uint32_t)__cvta_generic_to_shared(smem);
    float* hs   = (float*)(smem + OFF_H);
    int*   s_ix = (int*)(smem + OFF_SI);

    const int tid  = threadIdx.x;
    const int wid  = tid >> 5;     // 0..7 : token rows 16*wid
    const int lane = tid & 31;
    const int n0   = blockIdx.x * BMT;

    // ---- prologue: x [128][64] fp32 -> 3 bf16 split tiles (SW128) ----
    const float4* in4 = reinterpret_cast<const float4*>(input + (size_t)n0 * D);
    #pragma unroll
    for (int t = 0; t < 8; t++) {
        int idx = t * THREADS + tid;       // 0..2047 float4
        float4 v = in4[idx];
        int row = idx >> 4;                // token 0..127
        int c   = (idx & 15) << 2;         // starting d
        float vv[4] = {v.x, v.y, v.z, v.w};
        __nv_bfloat16 s0[4], s1[4], s2[4];
        #pragma unroll
        for (int q = 0; q < 4; q++) {
            float a = vv[q];
            s0[q] = __float2bfloat16(a);
            float r = a - __bfloat162float(s0[q]);
            s1[q] = __float2bfloat16(r);
            s2[q] = __float2bfloat16(r - __bfloat162float(s1[q]));
        }
        uint32_t off = SWZ((uint32_t)(row * 128 + c * 2));  // 8B-aligned, SWZ keeps pairs together
        char* b0p = smem + OFF_A + off;
        *(uint32_t*)(b0p)                       = pack_bf16x2(s0[0], s0[1]);
        *(uint32_t*)(b0p + 4)                   = pack_bf16x2(s0[2], s0[3]);
        *(uint32_t*)(b0p + TILE_BYTES)          = pack_bf16x2(s1[0], s1[1]);
        *(uint32_t*)(b0p + TILE_BYTES + 4)      = pack_bf16x2(s1[2], s1[3]);
        *(uint32_t*)(b0p + 2 * TILE_BYTES)      = pack_bf16x2(s2[0], s2[1]);
        *(uint32_t*)(b0p + 2 * TILE_BYTES + 4)  = pack_bf16x2(s2[2], s2[3]);
    }
    #pragma unroll
    for (int t = tid; t < K; t += THREADS) hs[t] = g_h[t];

    // ---- prefetch B chunk 0: 3 splits x 64 rows x 8 granules = 1536 ----
    const __nv_bfloat16* gsrc[3] = {g_e0, g_e1, g_e2};
    #pragma unroll
    for (int i = 0; i < 6; i++) {
        int idx = i * THREADS + tid;
        int sp = idx >> 9, rem = idx & 511;
        int row = rem >> 3, g = rem & 7;
        cp16(sb + OFF_B + sp * BTILE_BYTES + SWZ((uint32_t)(row * 128 + g * 16)),
             gsrc[sp] + (size_t)row * 64 + g * 8);
    }
    CP_COMMIT();

    __syncthreads();   // A tiles + hs visible

    // lane-derived fragment address pieces
    const int l7      = lane & 7;
    const int aRowSel = ((lane >> 3) & 1) << 3;   // A: mat&1 -> +8 rows
    const int aKSel   = (lane >> 4) << 4;         // A: mat>>1 -> +16 bytes
    const int bRowSel = (lane >> 4) << 3;         // B: mat>>1 -> +8 rows
    const int bKSel   = ((lane >> 3) & 1) << 4;   // B: mat&1 -> +16 bytes

    // ---- A fragments: chunk-invariant, loaded ONCE (48 regs) ----
    uint32_t afr[3][4][4];    // [split][ks][frag]
    #pragma unroll
    for (int s = 0; s < 3; s++)
        #pragma unroll
        for (int ks = 0; ks < 4; ks++) {
            uint32_t addr = sb + (uint32_t)(OFF_A + s * TILE_BYTES)
                + SWZ((uint32_t)((wid * 16 + aRowSel + l7) * 128 + ks * 32 + aKSel));
            ldsm4(afr[s][ks], addr);
        }

    // per-thread best over 2 row-slots: row = wid*16 + slot*8 + lane/4
    float bs[2] = {3.4e38f, 3.4e38f};
    int   bi[2] = {0, 0};

    for (int c = 0; c < NCHUNK; c++) {
        CP_WAIT0();
        __syncthreads();   // chunk c staged; everyone done with the other buffer

        if (c + 1 < NCHUNK) {
            int kb = (c + 1) * CHN;
            uint32_t bufo = (uint32_t)(OFF_B + ((c + 1) & 1) * 3 * BTILE_BYTES);
            #pragma unroll
            for (int i = 0; i < 6; i++) {
                int idx = i * THREADS + tid;
                int sp = idx >> 9, rem = idx & 511;
                int row = rem >> 3, g = rem & 7;
                cp16(sb + bufo + sp * BTILE_BYTES + SWZ((uint32_t)(row * 128 + g * 16)),
                     gsrc[sp] + (size_t)(kb + row) * 64 + g * 8);
            }
            CP_COMMIT();
        }

        const uint32_t bbase = sb + (uint32_t)(OFF_B + (c & 1) * 3 * BTILE_BYTES);

        float acc[8][4];   // 8 n-frags (8 cols each) x 4
        #pragma unroll
        for (int j = 0; j < 8; j++)
            #pragma unroll
            for (int q = 0; q < 4; q++) acc[j][q] = 0.f;

        // (A-split s, B-split t) with s + t <= 2; B loaded once per (t, ks)
        #pragma unroll
        for (int t = 0; t < 3; t++) {
            #pragma unroll
            for (int ks = 0; ks < 4; ks++) {
                uint32_t bf[4][4];
                #pragma unroll
                for (int jj = 0; jj < 4; jj++) {
                    uint32_t addr = bbase + (uint32_t)(t * BTILE_BYTES)
                        + SWZ((uint32_t)((jj * 16 + bRowSel + l7) * 128 + ks * 32 + bKSel));
                    ldsm4(bf[jj], addr);
                }
                #pragma unroll
                for (int s = 0; s < 3; s++) {
                    if (s + t <= 2) {
                        #pragma unroll
                        for (int jj = 0; jj < 4; jj++) {
                            mma16816(acc[jj * 2 + 0], afr[s][ks], bf[jj][0], bf[jj][1]);
                            mma16816(acc[jj * 2 + 1], afr[s][ks], bf[jj][2], bf[jj][3]);
                        }
                    }
                }
            }
        }

        // ---- scores + running argmin (lexicographic -> reference tie-break) ----
        #pragma unroll
        for (int j = 0; j < 8; j++) {
            int k0 = c * CHN + j * 8 + (lane & 3) * 2;
            float h0 = hs[k0], h1 = hs[k0 + 1];
            float s00 = h0 - acc[j][0];   // row lane/4,     col k0
            float s01 = h1 - acc[j][1];
            float s10 = h0 - acc[j][2];   // row lane/4 + 8
            float s11 = h1 - acc[j][3];
            if (s00 < bs[0] || (s00 == bs[0] && k0     < bi[0])) { bs[0] = s00; bi[0] = k0; }
            if (s01 < bs[0] || (s01 == bs[0] && k0 + 1 < bi[0])) { bs[0] = s01; bi[0] = k0 + 1; }
            if (s10 < bs[1] || (s10 == bs[1] && k0     < bi[1])) { bs[1] = s10; bi[1] = k0; }
            if (s11 < bs[1] || (s11 == bs[1] && k0 + 1 < bi[1])) { bs[1] = s11; bi[1] = k0 + 1; }
        }
        // no bottom sync: top-of-loop sync of iter c+1 protects buffer reuse
    }

    // ---- reduce across the 4 lanes sharing a row (xor 1, 2) ----
    #pragma unroll
    for (int sl = 0; sl < 2; sl++) {
        float s = bs[sl]; int ix = bi[sl];
        #pragma unroll
        for (int m = 1; m <= 2; m <<= 1) {
            float so = __shfl_xor_sync(0xffffffffu, s, m);
            int   io = __shfl_xor_sync(0xffffffffu, ix, m);
            if (so < s || (so == s && io < ix)) { s = so; ix = io; }
        }
        if ((lane & 3) == 0) {
            int row = wid * 16 + sl * 8 + (lane >> 2);
            s_ix[row] = ix;
        }
    }
    __syncthreads();
    if (ind_out && tid < BMT) ind_out[n0 + tid] = (float)s_ix[tid];

    // ---- gather quantize + diff (coalesced float4) ----
    #pragma unroll
    for (int t = 0; t < 8; t++) {
        int idx = t * THREADS + tid;
        int row = idx >> 4;
        int cc  = (idx & 15) << 2;
        int kq  = s_ix[row];
        float4 q = *(const float4*)(g_embedT + kq * D + cc);
        float4 x = in4[idx];
        size_t o = (size_t)(n0 + row) * D + cc;
        *reinterpret_cast<float4*>(&q_out[o]) = q;
        if (diff_out) {
            float4 df;
            df.x = (q.x - x.x) * (q.x - x.x);
            df.y = (q.y - x.y) * (q.y - x.y);
            df.z = (q.z - x.z) * (q.z - x.z);
            df.w = (q.w - x.w) * (q.w - x.w);
            *reinterpret_cast<float4*>(&diff_out[o]) = df;
        }
    }
}

extern "C" void kernel_launch(void* const* d_in, const int* in_sizes, int n_in,
                              void* d_out, int out_size) {
    const float* input = (const float*)d_in[0];   // [B,T,D] fp32
    const float* embed = (const float*)d_in[1];   // [D,K]   fp32

    const int N = in_sizes[0] / D;
    const long nd = (long)N * D;

    float* out = (float*)d_out;
    float* q_out    = out;
    float* diff_out = nullptr;
    float* ind_out  = nullptr;
    if ((long)out_size >= 2 * nd + N) { diff_out = out + nd; ind_out = out + 2 * nd; }
    else if ((long)out_size >= 2 * nd) { diff_out = out + nd; }

    cudaFuncSetAttribute(vq_main, cudaFuncAttributeMaxDynamicSharedMemorySize, SMEM_TOTAL);

    vq_prep<<<(K * D + 255) / 256, 256>>>(embed);
    vq_main<<<N / BMT, THREADS, SMEM_TOTAL>>>(input, q_out, diff_out, ind_out);
}

// round 11
// speedup vs baseline: 1.9743x; 1.0282x over previous
#include <cuda_runtime.h>
#include <cuda_bf16.h>
#include <cstdint>

// B=16, T=4096 -> N=65536 tokens, D=64, K=1024
#define D 64
#define K 1024
#define BMT 128          // tokens per CTA
#define CHN 64           // codes per chunk
#define NCHUNK (K / CHN) // 16
#define THREADS 256      // 8 warps, all M (16 token rows each); each spans all 64 chunk codes

#define TILE_BYTES 16384             // 128 rows x 128 B (bf16 x 64), SW128-swizzled
#define BTILE_BYTES 8192             // 64 rows x 128 B

#define OFF_H    0                   // K floats (4 KB)
#define OFF_SI   4096                // s_idx[128]
#define OFF_A    5120                // 3 A split tiles (48 KB), 1024-aligned
#define OFF_B    (OFF_A + 3 * TILE_BYTES)          // 2 buf x 3 splits x 8 KB
#define SMEM_TOTAL (OFF_B + 6 * BTILE_BYTES)       // 103424 B -> 2 CTAs/SM

#define SWZ(b) ((b) ^ (((b) >> 3) & 0x70))

__device__ float          g_embedT[K * D];   // [k][d] fp32 for gather
__device__ float          g_h[K];            // 0.5 * ||e_k||^2
__device__ __nv_bfloat16  g_e0[K * D];       // [k][d] bf16 split hi
__device__ __nv_bfloat16  g_e1[K * D];       // mid
__device__ __nv_bfloat16  g_e2[K * D];       // lo

__device__ __forceinline__ void cp16(uint32_t s, const void* g) {
    asm volatile("cp.async.cg.shared.global [%0], [%1], 16;" :: "r"(s), "l"(g));
}
#define CP_COMMIT()  asm volatile("cp.async.commit_group;")
#define CP_WAIT0()   asm volatile("cp.async.wait_group 0;")

__device__ __forceinline__ void ldsm4(uint32_t r[4], uint32_t addr) {
    asm volatile("ldmatrix.sync.aligned.m8n8.x4.shared.b16 {%0,%1,%2,%3}, [%4];"
        : "=r"(r[0]), "=r"(r[1]), "=r"(r[2]), "=r"(r[3]) : "r"(addr));
}
__device__ __forceinline__ void mma16816(float c[4], const uint32_t a[4],
                                         uint32_t b0, uint32_t b1) {
    asm volatile("mma.sync.aligned.m16n8k16.row.col.f32.bf16.bf16.f32 "
        "{%0,%1,%2,%3}, {%4,%5,%6,%7}, {%8,%9}, {%0,%1,%2,%3};"
        : "+f"(c[0]), "+f"(c[1]), "+f"(c[2]), "+f"(c[3])
        : "r"(a[0]), "r"(a[1]), "r"(a[2]), "r"(a[3]), "r"(b0), "r"(b1));
}
__device__ __forceinline__ uint32_t pack_bf16x2(__nv_bfloat16 lo, __nv_bfloat16 hi) {
    return (uint32_t)__bfloat16_as_ushort(lo) | ((uint32_t)__bfloat16_as_ushort(hi) << 16);
}

// ------------- prep: splits [k][d], transpose, norms -------------
__global__ void vq_prep(const float* __restrict__ embed) {
    int i = blockIdx.x * blockDim.x + threadIdx.x;
    if (i < K * D) {
        int k = i >> 6;
        int d = i & 63;
        float v = embed[d * K + k];
        g_embedT[i] = v;
        __nv_bfloat16 b0 = __float2bfloat16(v);
        float r = v - __bfloat162float(b0);
        __nv_bfloat16 b1 = __float2bfloat16(r);
        float r2 = r - __bfloat162float(b1);
        g_e0[i] = b0; g_e1[i] = b1; g_e2[i] = __float2bfloat16(r2);
    }
    if (i < K) {
        float s = 0.f;
        #pragma unroll
        for (int d = 0; d < D; d++) {
            float v = embed[d * K + i];
            s = fmaf(v, v, s);
        }
        g_h[i] = 0.5f * s;
    }
}

// ------------- main: split-bf16 HMMA distance GEMM + argmin + gather -------------
__global__ __launch_bounds__(THREADS, 2)
void vq_main(const float* __restrict__ input,
             float* __restrict__ q_out,
             float* __restrict__ diff_out,
             float* __restrict__ ind_out) {
    extern __shared__ char smem[];
    const uint32_t sb = (uint32_t)__cvta_generic_to_shared(smem);
    float* hs   = (float*)(smem + OFF_H);
    int*   s_ix = (int*)(smem + OFF_SI);

    const int tid  = threadIdx.x;
    const int wid  = tid >> 5;     // 0..7 : token rows 16*wid
    const int lane = tid & 31;
    const int n0   = blockIdx.x * BMT;

    // ---- prologue: x [128][64] fp32 -> 3 bf16 split tiles (SW128) ----
    const float4* in4 = reinterpret_cast<const float4*>(input + (size_t)n0 * D);
    #pragma unroll
    for (int t = 0; t < 8; t++) {
        int idx = t * THREADS + tid;       // 0..2047 float4
        float4 v = in4[idx];
        int row = idx >> 4;                // token 0..127
        int c   = (idx & 15) << 2;         // starting d
        float vv[4] = {v.x, v.y, v.z, v.w};
        __nv_bfloat16 s0[4], s1[4], s2[4];
        #pragma unroll
        for (int q = 0; q < 4; q++) {
            float a = vv[q];
            s0[q] = __float2bfloat16(a);
            float r = a - __bfloat162float(s0[q]);
            s1[q] = __float2bfloat16(r);
            s2[q] = __float2bfloat16(r - __bfloat162float(s1[q]));
        }
        uint32_t off = SWZ((uint32_t)(row * 128 + c * 2));
        char* b0p = smem + OFF_A + off;
        *(uint32_t*)(b0p)                       = pack_bf16x2(s0[0], s0[1]);
        *(uint32_t*)(b0p + 4)                   = pack_bf16x2(s0[2], s0[3]);
        *(uint32_t*)(b0p + TILE_BYTES)          = pack_bf16x2(s1[0], s1[1]);
        *(uint32_t*)(b0p + TILE_BYTES + 4)      = pack_bf16x2(s1[2], s1[3]);
        *(uint32_t*)(b0p + 2 * TILE_BYTES)      = pack_bf16x2(s2[0], s2[1]);
        *(uint32_t*)(b0p + 2 * TILE_BYTES + 4)  = pack_bf16x2(s2[2], s2[3]);
    }
    #pragma unroll
    for (int t = tid; t < K; t += THREADS) hs[t] = g_h[t];

    // ---- prefetch B chunk 0: 3 splits x 64 rows x 8 granules = 1536 ----
    const __nv_bfloat16* gsrc[3] = {g_e0, g_e1, g_e2};
    #pragma unroll
    for (int i = 0; i < 6; i++) {
        int idx = i * THREADS + tid;
        int sp = idx >> 9, rem = idx & 511;
        int row = rem >> 3, g = rem & 7;
        cp16(sb + OFF_B + sp * BTILE_BYTES + SWZ((uint32_t)(row * 128 + g * 16)),
             gsrc[sp] + (size_t)row * 64 + g * 8);
    }
    CP_COMMIT();

    __syncthreads();   // A tiles + hs visible

    // lane-derived fragment address pieces
    const int l7      = lane & 7;
    const int aRowSel = ((lane >> 3) & 1) << 3;   // A: mat&1 -> +8 rows
    const int aKSel   = (lane >> 4) << 4;         // A: mat>>1 -> +16 bytes
    const int bRowSel = (lane >> 4) << 3;         // B: mat>>1 -> +8 rows
    const int bKSel   = ((lane >> 3) & 1) << 4;   // B: mat&1 -> +16 bytes

    // ---- A fragments splits 0,1: chunk-invariant, loaded ONCE (32 regs) ----
    uint32_t afr[2][4][4];    // [split][ks][frag]
    #pragma unroll
    for (int s = 0; s < 2; s++)
        #pragma unroll
        for (int ks = 0; ks < 4; ks++) {
            uint32_t addr = sb + (uint32_t)(OFF_A + s * TILE_BYTES)
                + SWZ((uint32_t)((wid * 16 + aRowSel + l7) * 128 + ks * 32 + aKSel));
            ldsm4(afr[s][ks], addr);
        }
    // split-2 A frag addresses (loaded transiently per stage)
    uint32_t a2addr[4];
    #pragma unroll
    for (int ks = 0; ks < 4; ks++)
        a2addr[ks] = sb + (uint32_t)(OFF_A + 2 * TILE_BYTES)
            + SWZ((uint32_t)((wid * 16 + aRowSel + l7) * 128 + ks * 32 + aKSel));

    // per-thread best over 2 row-slots: row = wid*16 + slot*8 + lane/4
    float bs[2] = {3.4e38f, 3.4e38f};
    int   bi[2] = {0, 0};

    for (int c = 0; c < NCHUNK; c++) {
        CP_WAIT0();
        __syncthreads();   // chunk c staged; everyone done with the other buffer

        if (c + 1 < NCHUNK) {
            int kb = (c + 1) * CHN;
            uint32_t bufo = (uint32_t)(OFF_B + ((c + 1) & 1) * 3 * BTILE_BYTES);
            #pragma unroll
            for (int i = 0; i < 6; i++) {
                int idx = i * THREADS + tid;
                int sp = idx >> 9, rem = idx & 511;
                int row = rem >> 3, g = rem & 7;
                cp16(sb + bufo + sp * BTILE_BYTES + SWZ((uint32_t)(row * 128 + g * 16)),
                     gsrc[sp] + (size_t)(kb + row) * 64 + g * 8);
            }
            CP_COMMIT();
        }

        const uint32_t bbase = sb + (uint32_t)(OFF_B + (c & 1) * 3 * BTILE_BYTES);

        float acc[8][4];
        #pragma unroll
        for (int j = 0; j < 8; j++)
            #pragma unroll
            for (int q = 0; q < 4; q++) acc[j][q] = 0.f;

        // ---- 12 stages (t,ks), t-major; B frags double-buffered in regs ----
        uint32_t bf[2][4][4];
        #pragma unroll
        for (int jj = 0; jj < 4; jj++)
            ldsm4(bf[0][jj], bbase
                + SWZ((uint32_t)((jj * 16 + bRowSel + l7) * 128 + bKSel)));

        #pragma unroll
        for (int st = 0; st < 12; st++) {
            const int t  = st >> 2;
            const int ks = st & 3;

            // prefetch next stage's B frags into the other buffer
            if (st + 1 < 12) {
                const int tn = (st + 1) >> 2, kn = (st + 1) & 3;
                #pragma unroll
                for (int jj = 0; jj < 4; jj++)
                    ldsm4(bf[(st + 1) & 1][jj], bbase + (uint32_t)(tn * BTILE_BYTES)
                        + SWZ((uint32_t)((jj * 16 + bRowSel + l7) * 128 + kn * 32 + bKSel)));
            }
            uint32_t a2[4];
            if (t == 0) ldsm4(a2, a2addr[ks]);   // covered by the s=0/s=1 MMAs below

            uint32_t (*bc)[4] = bf[st & 1];
            // s = 0  (always)
            #pragma unroll
            for (int jj = 0; jj < 4; jj++) {
                mma16816(acc[jj * 2 + 0], afr[0][ks], bc[jj][0], bc[jj][1]);
                mma16816(acc[jj * 2 + 1], afr[0][ks], bc[jj][2], bc[jj][3]);
            }
            // s = 1  (t <= 1)
            if (t <= 1) {
                #pragma unroll
                for (int jj = 0; jj < 4; jj++) {
                    mma16816(acc[jj * 2 + 0], afr[1][ks], bc[jj][0], bc[jj][1]);
                    mma16816(acc[jj * 2 + 1], afr[1][ks], bc[jj][2], bc[jj][3]);
                }
            }
            // s = 2  (t == 0)
            if (t == 0) {
                #pragma unroll
                for (int jj = 0; jj < 4; jj++) {
                    mma16816(acc[jj * 2 + 0], a2, bc[jj][0], bc[jj][1]);
                    mma16816(acc[jj * 2 + 1], a2, bc[jj][2], bc[jj][3]);
                }
            }
        }

        // ---- scores + running argmin (strict < ; per-thread k ascending) ----
        #pragma unroll
        for (int j = 0; j < 8; j++) {
            int k0 = c * CHN + j * 8 + (lane & 3) * 2;
            float h0 = hs[k0], h1 = hs[k0 + 1];
            float s00 = h0 - acc[j][0];   // row lane/4,     col k0
            float s01 = h1 - acc[j][1];
            float s10 = h0 - acc[j][2];   // row lane/4 + 8
            float s11 = h1 - acc[j][3];
            if (s00 < bs[0]) { bs[0] = s00; bi[0] = k0; }
            if (s01 < bs[0]) { bs[0] = s01; bi[0] = k0 + 1; }
            if (s10 < bs[1]) { bs[1] = s10; bi[1] = k0; }
            if (s11 < bs[1]) { bs[1] = s11; bi[1] = k0 + 1; }
        }
        // no bottom sync: top-of-loop sync of iter c+1 protects buffer reuse
    }

    // ---- reduce across the 4 lanes sharing a row (xor 1, 2) ----
    #pragma unroll
    for (int sl = 0; sl < 2; sl++) {
        float s = bs[sl]; int ix = bi[sl];
        #pragma unroll
        for (int m = 1; m <= 2; m <<= 1) {
            float so = __shfl_xor_sync(0xffffffffu, s, m);
            int   io = __shfl_xor_sync(0xffffffffu, ix, m);
            if (so < s || (so == s && io < ix)) { s = so; ix = io; }
        }
        if ((lane & 3) == 0) {
            int row = wid * 16 + sl * 8 + (lane >> 2);
            s_ix[row] = ix;
        }
    }
    __syncthreads();
    if (ind_out && tid < BMT) ind_out[n0 + tid] = (float)s_ix[tid];

    // ---- gather quantize + diff (coalesced float4) ----
    #pragma unroll
    for (int t = 0; t < 8; t++) {
        int idx = t * THREADS + tid;
        int row = idx >> 4;
        int cc  = (idx & 15) << 2;
        int kq  = s_ix[row];
        float4 q = *(const float4*)(g_embedT + kq * D + cc);
        float4 x = in4[idx];
        size_t o = (size_t)(n0 + row) * D + cc;
        *reinterpret_cast<float4*>(&q_out[o]) = q;
        if (diff_out) {
            float4 df;
            df.x = (q.x - x.x) * (q.x - x.x);
            df.y = (q.y - x.y) * (q.y - x.y);
            df.z = (q.z - x.z) * (q.z - x.z);
            df.w = (q.w - x.w) * (q.w - x.w);
            *reinterpret_cast<float4*>(&diff_out[o]) = df;
        }
    }
}

extern "C" void kernel_launch(void* const* d_in, const int* in_sizes, int n_in,
                              void* d_out, int out_size) {
    const float* input = (const float*)d_in[0];   // [B,T,D] fp32
    const float* embed = (const float*)d_in[1];   // [D,K]   fp32

    const int N = in_sizes[0] / D;
    const long nd = (long)N * D;

    float* out = (float*)d_out;
    float* q_out    = out;
    float* diff_out = nullptr;
    float* ind_out  = nullptr;
    if ((long)out_size >= 2 * nd + N) { diff_out = out + nd; ind_out = out + 2 * nd; }
    else if ((long)out_size >= 2 * nd) { diff_out = out + nd; }

    cudaFuncSetAttribute(vq_main, cudaFuncAttributeMaxDynamicSharedMemorySize, SMEM_TOTAL);

    vq_prep<<<(K * D + 255) / 256, 256>>>(embed);
    vq_main<<<N / BMT, THREADS, SMEM_TOTAL>>>(input, q_out, diff_out, ind_out);
}

// round 12
// speedup vs baseline: 2.2959x; 1.1629x over previous
#include <cuda_runtime.h>
#include <cuda_bf16.h>
#include <cstdint>

// B=16, T=4096 -> N=65536 tokens, D=64, K=1024
#define D 64
#define K 1024
#define BMT 128          // tokens per CTA
#define CHN 128          // codes per chunk
#define NCHUNK 8
#define NSTAGE 16        // 2 passes x 8 chunks
#define THREADS 256      // 8 warps, all M (16 token rows each)
#define CAP 32           // candidate list capacity per token
#define EPS_C 0.0170f    // >= 2*(2*2^-8+2^-16) + slack

#define TILE_BYTES 16384             // 128 rows x 128 B bf16, SW128
#define OFF_H    0                   // K floats (4 KB)
#define OFF_N2   4096                // ||x||^2 per row (512 B)
#define OFF_TH   4608                // phase-1 best -> threshold (512 B)
#define OFF_CNT  5120                // candidate counts (512 B)
#define OFF_SI   5632                // final index (512 B)
#define OFF_CAND 6144                // 128 x CAP ints (16 KB)
#define OFF_A    22528               // x0 tile (16 KB), 1024-aligned
#define OFF_B    38912               // 2 x 16 KB B buffers
#define SMEM_TOTAL (OFF_B + 2 * TILE_BYTES)   // 71680 -> 2 CTAs/SM

#define SWZ(b) ((b) ^ (((b) >> 3) & 0x70))

__device__ float          g_embedT[K * D];   // [k][d] fp32 (gather + exact eval)
__device__ float          g_h[K];            // 0.5 * ||e_k||^2
__device__ __nv_bfloat16  g_e0[K * D];       // [k][d] bf16 hi split
__device__ int            g_emax_bits = 0;   // max ||e_k|| as float bits

__device__ __forceinline__ void cp16(uint32_t s, const void* g) {
    asm volatile("cp.async.cg.shared.global [%0], [%1], 16;" :: "r"(s), "l"(g));
}
#define CP_COMMIT()  asm volatile("cp.async.commit_group;")
#define CP_WAIT0()   asm volatile("cp.async.wait_group 0;")

__device__ __forceinline__ void ldsm4(uint32_t r[4], uint32_t addr) {
    asm volatile("ldmatrix.sync.aligned.m8n8.x4.shared.b16 {%0,%1,%2,%3}, [%4];"
        : "=r"(r[0]), "=r"(r[1]), "=r"(r[2]), "=r"(r[3]) : "r"(addr));
}
__device__ __forceinline__ void mma16816(float c[4], const uint32_t a[4],
                                         uint32_t b0, uint32_t b1) {
    asm volatile("mma.sync.aligned.m16n8k16.row.col.f32.bf16.bf16.f32 "
        "{%0,%1,%2,%3}, {%4,%5,%6,%7}, {%8,%9}, {%0,%1,%2,%3};"
        : "+f"(c[0]), "+f"(c[1]), "+f"(c[2]), "+f"(c[3])
        : "r"(a[0]), "r"(a[1]), "r"(a[2]), "r"(a[3]), "r"(b0), "r"(b1));
}
__device__ __forceinline__ uint32_t pack_bf16x2(__nv_bfloat16 lo, __nv_bfloat16 hi) {
    return (uint32_t)__bfloat16_as_ushort(lo) | ((uint32_t)__bfloat16_as_ushort(hi) << 16);
}

// ------------- prep: hi split [k][d], transpose, norms, max-norm -------------
__global__ void vq_prep(const float* __restrict__ embed) {
    int i = blockIdx.x * blockDim.x + threadIdx.x;
    if (i < K * D) {
        int k = i >> 6;
        int d = i & 63;
        float v = embed[d * K + k];
        g_embedT[i] = v;
        g_e0[i] = __float2bfloat16(v);
    }
    if (i < K) {
        float s = 0.f;
        #pragma unroll
        for (int d = 0; d < D; d++) {
            float v = embed[d * K + i];
            s = fmaf(v, v, s);
        }
        g_h[i] = 0.5f * s;
        atomicMax(&g_emax_bits, __float_as_int(sqrtf(s)));
    }
}

__device__ __forceinline__ float score_exact(const float4* x4, int k, const float* hs) {
    const float4* e4 = (const float4*)(g_embedT + k * D);
    float dot = 0.f;
    #pragma unroll
    for (int i = 0; i < 16; i++) {
        float4 a = x4[i], b = e4[i];
        dot = fmaf(a.x, b.x, dot);
        dot = fmaf(a.y, b.y, dot);
        dot = fmaf(a.z, b.z, dot);
        dot = fmaf(a.w, b.w, dot);
    }
    return hs[k] - dot;
}

// ------------- main: hi-split HMMA + pruning + exact verify + gather -------------
__global__ __launch_bounds__(THREADS, 2)
void vq_main(const float* __restrict__ input,
             float* __restrict__ q_out,
             float* __restrict__ diff_out,
             float* __restrict__ ind_out) {
    extern __shared__ char smem[];
    const uint32_t sb = (uint32_t)__cvta_generic_to_shared(smem);
    float* hs   = (float*)(smem + OFF_H);
    float* n2   = (float*)(smem + OFF_N2);
    float* th   = (float*)(smem + OFF_TH);
    int*   cnt  = (int*)(smem + OFF_CNT);
    int*   s_ix = (int*)(smem + OFF_SI);
    int*   cand = (int*)(smem + OFF_CAND);

    const int tid  = threadIdx.x;
    const int wid  = tid >> 5;     // 0..7 : token rows 16*wid
    const int lane = tid & 31;
    const int n0   = blockIdx.x * BMT;

    if (tid < BMT) { n2[tid] = 0.f; cnt[tid] = 0; }
    __syncthreads();

    // ---- prologue: x -> bf16 hi tile (SW128) + per-row ||x||^2 ----
    const float4* in4 = reinterpret_cast<const float4*>(input + (size_t)n0 * D);
    #pragma unroll
    for (int t = 0; t < 8; t++) {
        int idx = t * THREADS + tid;       // 0..2047 float4
        float4 v = in4[idx];
        int row = idx >> 4;
        int c   = (idx & 15) << 2;
        float p = v.x * v.x + v.y * v.y + v.z * v.z + v.w * v.w;
        atomicAdd(&n2[row], p);
        uint32_t off = SWZ((uint32_t)(row * 128 + c * 2));
        *(uint32_t*)(smem + OFF_A + off)     = pack_bf16x2(__float2bfloat16(v.x), __float2bfloat16(v.y));
        *(uint32_t*)(smem + OFF_A + off + 4) = pack_bf16x2(__float2bfloat16(v.z), __float2bfloat16(v.w));
    }
    #pragma unroll
    for (int t = tid; t < K; t += THREADS) hs[t] = g_h[t];

    // ---- prefetch B chunk 0: 128 rows x 8 granules = 1024 ----
    #pragma unroll
    for (int i = 0; i < 4; i++) {
        int idx = i * THREADS + tid;
        int row = idx >> 3, g = idx & 7;
        cp16(sb + OFF_B + SWZ((uint32_t)(row * 128 + g * 16)),
             g_e0 + (size_t)row * 64 + g * 8);
    }
    CP_COMMIT();

    const float emax = __int_as_float(g_emax_bits);

    // lane-derived fragment address pieces
    const int l7      = lane & 7;
    const int aRowSel = ((lane >> 3) & 1) << 3;
    const int aKSel   = (lane >> 4) << 4;
    const int bRowSel = (lane >> 4) << 3;
    const int bKSel   = ((lane >> 3) & 1) << 4;

    __syncthreads();   // A tile + hs visible

    // ---- A fragments (1 split), chunk-invariant: 16 regs ----
    uint32_t afr[4][4];
    #pragma unroll
    for (int ks = 0; ks < 4; ks++)
        ldsm4(afr[ks], sb + (uint32_t)OFF_A
            + SWZ((uint32_t)((wid * 16 + aRowSel + l7) * 128 + ks * 32 + aKSel)));

    const int row0 = wid * 16 + (lane >> 2);
    const int row1 = row0 + 8;

    float bs0 = 3.4e38f, bs1 = 3.4e38f;   // phase-1 running min (value only)

    for (int cs = 0; cs < NSTAGE; cs++) {
        CP_WAIT0();
        __syncthreads();   // chunk staged; everyone done with the other buffer

        if (cs + 1 < NSTAGE) {
            int kb = ((cs + 1) & 7) * CHN;
            uint32_t bufo = (uint32_t)(OFF_B + ((cs + 1) & 1) * TILE_BYTES);
            #pragma unroll
            for (int i = 0; i < 4; i++) {
                int idx = i * THREADS + tid;
                int row = idx >> 3, g = idx & 7;
                cp16(sb + bufo + SWZ((uint32_t)(row * 128 + g * 16)),
                     g_e0 + (size_t)(kb + row) * 64 + g * 8);
            }
            CP_COMMIT();
        }

        const uint32_t bbase = sb + (uint32_t)(OFF_B + (cs & 1) * TILE_BYTES);

        float acc[16][4];
        #pragma unroll
        for (int j = 0; j < 16; j++)
            #pragma unroll
            for (int q = 0; q < 4; q++) acc[j][q] = 0.f;

        #pragma unroll
        for (int ks = 0; ks < 4; ks++) {
            uint32_t bf[8][4];
            #pragma unroll
            for (int jj = 0; jj < 8; jj++)
                ldsm4(bf[jj], bbase
                    + SWZ((uint32_t)((jj * 16 + bRowSel + l7) * 128 + ks * 32 + bKSel)));
            #pragma unroll
            for (int jj = 0; jj < 8; jj++) {
                mma16816(acc[jj * 2 + 0], afr[ks], bf[jj][0], bf[jj][1]);
                mma16816(acc[jj * 2 + 1], afr[ks], bf[jj][2], bf[jj][3]);
            }
        }

        const int c = cs & 7;
        if (cs < 8) {
            // ---- phase 1: running min of approx scores ----
            #pragma unroll
            for (int j = 0; j < 16; j++) {
                int k0 = c * CHN + j * 8 + (lane & 3) * 2;
                bs0 = fminf(bs0, fminf(hs[k0] - acc[j][0], hs[k0 + 1] - acc[j][1]));
                bs1 = fminf(bs1, fminf(hs[k0] - acc[j][2], hs[k0 + 1] - acc[j][3]));
            }
            if (cs == 7) {
                // reduce min across the 4 lanes of each row, set thresholds
                float r0 = bs0, r1 = bs1;
                #pragma unroll
                for (int m = 1; m <= 2; m <<= 1) {
                    r0 = fminf(r0, __shfl_xor_sync(0xffffffffu, r0, m));
                    r1 = fminf(r1, __shfl_xor_sync(0xffffffffu, r1, m));
                }
                if ((lane & 3) == 0) {
                    th[row0] = r0 + EPS_C * sqrtf(n2[row0]) * emax;
                    th[row1] = r1 + EPS_C * sqrtf(n2[row1]) * emax;
                }
            }
        } else {
            // ---- phase 2: collect candidates below threshold ----
            float th0 = th[row0], th1 = th[row1];
            #pragma unroll
            for (int j = 0; j < 16; j++) {
                int k0 = c * CHN + j * 8 + (lane & 3) * 2;
                float h0 = hs[k0], h1 = hs[k0 + 1];
                if (h0 - acc[j][0] < th0) {
                    int p = atomicAdd(&cnt[row0], 1);
                    if (p < CAP) cand[row0 * CAP + p] = k0;
                }
                if (h1 - acc[j][1] < th0) {
                    int p = atomicAdd(&cnt[row0], 1);
                    if (p < CAP) cand[row0 * CAP + p] = k0 + 1;
                }
                if (h0 - acc[j][2] < th1) {
                    int p = atomicAdd(&cnt[row1], 1);
                    if (p < CAP) cand[row1 * CAP + p] = k0;
                }
                if (h1 - acc[j][3] < th1) {
                    int p = atomicAdd(&cnt[row1], 1);
                    if (p < CAP) cand[row1 * CAP + p] = k0 + 1;
                }
            }
        }
    }

    __syncthreads();

    // ---- exact verification: fp32 re-eval of candidates per token ----
    if (tid < BMT) {
        int row = tid;
        const float4* x4 = (const float4*)(input + (size_t)(n0 + row) * D);
        int n = cnt[row];
        float bsv = 3.4e38f;
        int   bix = 0;
        if (n <= CAP) {
            for (int j = 0; j < n; j++) {
                int k = cand[row * CAP + j];
                float s = score_exact(x4, k, hs);
                if (s < bsv || (s == bsv && k < bix)) { bsv = s; bix = k; }
            }
        } else {
            // overflow fallback: exact scan of all codes (ascending k, strict <)
            for (int k = 0; k < K; k++) {
                float s = score_exact(x4, k, hs);
                if (s < bsv) { bsv = s; bix = k; }
            }
        }
        s_ix[row] = bix;
        if (ind_out) ind_out[n0 + row] = (float)bix;
    }
    __syncthreads();

    // ---- gather quantize + diff (coalesced float4) ----
    #pragma unroll
    for (int t = 0; t < 8; t++) {
        int idx = t * THREADS + tid;
        int row = idx >> 4;
        int cc  = (idx & 15) << 2;
        int kq  = s_ix[row];
        float4 q = *(const float4*)(g_embedT + kq * D + cc);
        float4 x = in4[idx];
        size_t o = (size_t)(n0 + row) * D + cc;
        *reinterpret_cast<float4*>(&q_out[o]) = q;
        if (diff_out) {
            float4 df;
            df.x = (q.x - x.x) * (q.x - x.x);
            df.y = (q.y - x.y) * (q.y - x.y);
            df.z = (q.z - x.z) * (q.z - x.z);
            df.w = (q.w - x.w) * (q.w - x.w);
            *reinterpret_cast<float4*>(&diff_out[o]) = df;
        }
    }
}

extern "C" void kernel_launch(void* const* d_in, const int* in_sizes, int n_in,
                              void* d_out, int out_size) {
    const float* input = (const float*)d_in[0];   // [B,T,D] fp32
    const float* embed = (const float*)d_in[1];   // [D,K]   fp32

    const int N = in_sizes[0] / D;
    const long nd = (long)N * D;

    float* out = (float*)d_out;
    float* q_out    = out;
    float* diff_out = nullptr;
    float* ind_out  = nullptr;
    if ((long)out_size >= 2 * nd + N) { diff_out = out + nd; ind_out = out + 2 * nd; }
    else if ((long)out_size >= 2 * nd) { diff_out = out + nd; }

    cudaFuncSetAttribute(vq_main, cudaFuncAttributeMaxDynamicSharedMemorySize, SMEM_TOTAL);

    vq_prep<<<(K * D + 255) / 256, 256>>>(embed);
    vq_main<<<N / BMT, THREADS, SMEM_TOTAL>>>(input, q_out, diff_out, ind_out);
}

// round 13
// speedup vs baseline: 2.6079x; 1.1359x over previous
#include <cuda_runtime.h>
#include <cuda_bf16.h>
#include <cstdint>

// B=16, T=4096 -> N=65536 tokens, D=64, K=1024
#define D 64
#define K 1024
#define BMT 128          // tokens per CTA
#define CHN 128          // codes per chunk
#define NCHUNK 8         // single pass
#define THREADS 256      // 8 warps, all M (16 token rows each)
#define CAP 32           // candidate list capacity per token
#define EPS_C 0.0170f    // >= 2*(2*2^-8+2^-16) + slack

#define TILE_BYTES 16384             // 128 rows x 128 B bf16, SW128
#define OFF_H    0                   // K floats (4 KB)
#define OFF_N2   4096                // ||x||^2 per row (512 B)
#define OFF_CNT  4608                // candidate counts (512 B)
#define OFF_SI   5120                // final index (512 B)
#define OFF_CAND 5632                // 128 x CAP ints (16 KB)
#define OFF_A    22528               // x0 tile (16 KB), 1024-aligned
#define OFF_B    38912               // 2 x 16 KB B buffers
#define SMEM_TOTAL (OFF_B + 2 * TILE_BYTES)   // 71680 -> 2 CTAs/SM

#define SWZ(b) ((b) ^ (((b) >> 3) & 0x70))

__device__ float          g_embedT[K * D];   // [k][d] fp32 (gather + exact eval)
__device__ float          g_h[K];            // 0.5 * ||e_k||^2
__device__ __nv_bfloat16  g_e0[K * D];       // [k][d] bf16 hi split
__device__ int            g_emax_bits = 0;   // max ||e_k|| as float bits

__device__ __forceinline__ void cp16(uint32_t s, const void* g) {
    asm volatile("cp.async.cg.shared.global [%0], [%1], 16;" :: "r"(s), "l"(g));
}
#define CP_COMMIT()  asm volatile("cp.async.commit_group;")
#define CP_WAIT0()   asm volatile("cp.async.wait_group 0;")

__device__ __forceinline__ void ldsm4(uint32_t r[4], uint32_t addr) {
    asm volatile("ldmatrix.sync.aligned.m8n8.x4.shared.b16 {%0,%1,%2,%3}, [%4];"
        : "=r"(r[0]), "=r"(r[1]), "=r"(r[2]), "=r"(r[3]) : "r"(addr));
}
__device__ __forceinline__ void mma16816(float c[4], const uint32_t a[4],
                                         uint32_t b0, uint32_t b1) {
    asm volatile("mma.sync.aligned.m16n8k16.row.col.f32.bf16.bf16.f32 "
        "{%0,%1,%2,%3}, {%4,%5,%6,%7}, {%8,%9}, {%0,%1,%2,%3};"
        : "+f"(c[0]), "+f"(c[1]), "+f"(c[2]), "+f"(c[3])
        : "r"(a[0]), "r"(a[1]), "r"(a[2]), "r"(a[3]), "r"(b0), "r"(b1));
}
__device__ __forceinline__ uint32_t pack_bf16x2(__nv_bfloat16 lo, __nv_bfloat16 hi) {
    return (uint32_t)__bfloat16_as_ushort(lo) | ((uint32_t)__bfloat16_as_ushort(hi) << 16);
}

// ------------- prep: hi split [k][d], transpose, norms, max-norm -------------
__global__ void vq_prep(const float* __restrict__ embed) {
    int i = blockIdx.x * blockDim.x + threadIdx.x;
    if (i < K * D) {
        int k = i >> 6;
        int d = i & 63;
        float v = embed[d * K + k];
        g_embedT[i] = v;
        g_e0[i] = __float2bfloat16(v);
    }
    if (i < K) {
        float s = 0.f;
        #pragma unroll
        for (int d = 0; d < D; d++) {
            float v = embed[d * K + i];
            s = fmaf(v, v, s);
        }
        g_h[i] = 0.5f * s;
        atomicMax(&g_emax_bits, __float_as_int(sqrtf(s)));
    }
}

__device__ __forceinline__ float score_exact(const float4* x4, int k, const float* hs) {
    const float4* e4 = (const float4*)(g_embedT + k * D);
    float dot = 0.f;
    #pragma unroll
    for (int i = 0; i < 16; i++) {
        float4 a = x4[i], b = e4[i];
        dot = fmaf(a.x, b.x, dot);
        dot = fmaf(a.y, b.y, dot);
        dot = fmaf(a.z, b.z, dot);
        dot = fmaf(a.w, b.w, dot);
    }
    return hs[k] - dot;
}

// ------------- main: hi-split HMMA + streaming prune + exact verify + gather -------------
__global__ __launch_bounds__(THREADS, 2)
void vq_main(const float* __restrict__ input,
             float* __restrict__ q_out,
             float* __restrict__ diff_out,
             float* __restrict__ ind_out) {
    extern __shared__ char smem[];
    const uint32_t sb = (uint32_t)__cvta_generic_to_shared(smem);
    float* hs   = (float*)(smem + OFF_H);
    float* n2   = (float*)(smem + OFF_N2);
    int*   cnt  = (int*)(smem + OFF_CNT);
    int*   s_ix = (int*)(smem + OFF_SI);
    int*   cand = (int*)(smem + OFF_CAND);

    const int tid  = threadIdx.x;
    const int wid  = tid >> 5;     // 0..7 : token rows 16*wid
    const int lane = tid & 31;
    const int n0   = blockIdx.x * BMT;

    if (tid < BMT) { n2[tid] = 0.f; cnt[tid] = 0; }
    __syncthreads();

    // ---- prologue: x -> bf16 hi tile (SW128) + per-row ||x||^2 ----
    const float4* in4 = reinterpret_cast<const float4*>(input + (size_t)n0 * D);
    #pragma unroll
    for (int t = 0; t < 8; t++) {
        int idx = t * THREADS + tid;       // 0..2047 float4
        float4 v = in4[idx];
        int row = idx >> 4;
        int c   = (idx & 15) << 2;
        float p = v.x * v.x + v.y * v.y + v.z * v.z + v.w * v.w;
        atomicAdd(&n2[row], p);
        uint32_t off = SWZ((uint32_t)(row * 128 + c * 2));
        *(uint32_t*)(smem + OFF_A + off)     = pack_bf16x2(__float2bfloat16(v.x), __float2bfloat16(v.y));
        *(uint32_t*)(smem + OFF_A + off + 4) = pack_bf16x2(__float2bfloat16(v.z), __float2bfloat16(v.w));
    }
    #pragma unroll
    for (int t = tid; t < K; t += THREADS) hs[t] = g_h[t];

    // ---- prefetch B chunk 0: 128 rows x 8 granules = 1024 ----
    #pragma unroll
    for (int i = 0; i < 4; i++) {
        int idx = i * THREADS + tid;
        int row = idx >> 3, g = idx & 7;
        cp16(sb + OFF_B + SWZ((uint32_t)(row * 128 + g * 16)),
             g_e0 + (size_t)row * 64 + g * 8);
    }
    CP_COMMIT();

    const float emax = __int_as_float(g_emax_bits);

    // lane-derived fragment address pieces
    const int l7      = lane & 7;
    const int aRowSel = ((lane >> 3) & 1) << 3;
    const int aKSel   = (lane >> 4) << 4;
    const int bRowSel = (lane >> 4) << 3;
    const int bKSel   = ((lane >> 3) & 1) << 4;

    __syncthreads();   // A tile + hs + n2 visible

    // ---- A fragments (1 split), chunk-invariant: 16 regs ----
    uint32_t afr[4][4];
    #pragma unroll
    for (int ks = 0; ks < 4; ks++)
        ldsm4(afr[ks], sb + (uint32_t)OFF_A
            + SWZ((uint32_t)((wid * 16 + aRowSel + l7) * 128 + ks * 32 + aKSel)));

    const int row0 = wid * 16 + (lane >> 2);
    const int row1 = row0 + 8;
    const float eps0 = EPS_C * sqrtf(n2[row0]) * emax;
    const float eps1 = EPS_C * sqrtf(n2[row1]) * emax;

    float rb0 = 3.4e38f, rb1 = 3.4e38f;   // running prefix min per row

    for (int cs = 0; cs < NCHUNK; cs++) {
        CP_WAIT0();
        __syncthreads();   // chunk staged; everyone done with the other buffer

        if (cs + 1 < NCHUNK) {
            int kb = (cs + 1) * CHN;
            uint32_t bufo = (uint32_t)(OFF_B + ((cs + 1) & 1) * TILE_BYTES);
            #pragma unroll
            for (int i = 0; i < 4; i++) {
                int idx = i * THREADS + tid;
                int row = idx >> 3, g = idx & 7;
                cp16(sb + bufo + SWZ((uint32_t)(row * 128 + g * 16)),
                     g_e0 + (size_t)(kb + row) * 64 + g * 8);
            }
            CP_COMMIT();
        }

        const uint32_t bbase = sb + (uint32_t)(OFF_B + (cs & 1) * TILE_BYTES);

        float acc[16][4];
        #pragma unroll
        for (int j = 0; j < 16; j++)
            #pragma unroll
            for (int q = 0; q < 4; q++) acc[j][q] = 0.f;

        #pragma unroll
        for (int ks = 0; ks < 4; ks++) {
            uint32_t bf[8][4];
            #pragma unroll
            for (int jj = 0; jj < 8; jj++)
                ldsm4(bf[jj], bbase
                    + SWZ((uint32_t)((jj * 16 + bRowSel + l7) * 128 + ks * 32 + bKSel)));
            #pragma unroll
            for (int jj = 0; jj < 8; jj++) {
                mma16816(acc[jj * 2 + 0], afr[ks], bf[jj][0], bf[jj][1]);
                mma16816(acc[jj * 2 + 1], afr[ks], bf[jj][2], bf[jj][3]);
            }
        }

        // ---- scores in-place + chunk min ----
        float m0 = 3.4e38f, m1 = 3.4e38f;
        #pragma unroll
        for (int j = 0; j < 16; j++) {
            int k0 = cs * CHN + j * 8 + (lane & 3) * 2;
            float h0 = hs[k0], h1 = hs[k0 + 1];
            acc[j][0] = h0 - acc[j][0];
            acc[j][1] = h1 - acc[j][1];
            acc[j][2] = h0 - acc[j][2];
            acc[j][3] = h1 - acc[j][3];
            m0 = fminf(m0, fminf(acc[j][0], acc[j][1]));
            m1 = fminf(m1, fminf(acc[j][2], acc[j][3]));
        }
        // reduce chunk min across the 4 lanes of each row
        #pragma unroll
        for (int m = 1; m <= 2; m <<= 1) {
            m0 = fminf(m0, __shfl_xor_sync(0xffffffffu, m0, m));
            m1 = fminf(m1, __shfl_xor_sync(0xffffffffu, m1, m));
        }
        rb0 = fminf(rb0, m0);
        rb1 = fminf(rb1, m1);
        const float th0 = rb0 + eps0;
        const float th1 = rb1 + eps1;

        // ---- collect candidates below prefix threshold (superset of final set) ----
        #pragma unroll
        for (int j = 0; j < 16; j++) {
            int k0 = cs * CHN + j * 8 + (lane & 3) * 2;
            if (acc[j][0] < th0) {
                int p = atomicAdd(&cnt[row0], 1);
                if (p < CAP) cand[row0 * CAP + p] = k0;
            }
            if (acc[j][1] < th0) {
                int p = atomicAdd(&cnt[row0], 1);
                if (p < CAP) cand[row0 * CAP + p] = k0 + 1;
            }
            if (acc[j][2] < th1) {
                int p = atomicAdd(&cnt[row1], 1);
                if (p < CAP) cand[row1 * CAP + p] = k0;
            }
            if (acc[j][3] < th1) {
                int p = atomicAdd(&cnt[row1], 1);
                if (p < CAP) cand[row1 * CAP + p] = k0 + 1;
            }
        }
        // no bottom sync: top-of-loop sync of iter cs+1 protects buffer reuse
    }

    __syncthreads();

    // ---- exact verification: fp32 re-eval of candidates per token ----
    if (tid < BMT) {
        int row = tid;
        const float4* x4 = (const float4*)(input + (size_t)(n0 + row) * D);
        int n = cnt[row];
        float bsv = 3.4e38f;
        int   bix = 0;
        if (n <= CAP) {
            for (int j = 0; j < n; j++) {
                int k = cand[row * CAP + j];
                float s = score_exact(x4, k, hs);
                if (s < bsv || (s == bsv && k < bix)) { bsv = s; bix = k; }
            }
        } else {
            // overflow fallback: exact scan of all codes (ascending k, strict <)
            for (int k = 0; k < K; k++) {
                float s = score_exact(x4, k, hs);
                if (s < bsv) { bsv = s; bix = k; }
            }
        }
        s_ix[row] = bix;
        if (ind_out) ind_out[n0 + row] = (float)bix;
    }
    __syncthreads();

    // ---- gather quantize + diff (coalesced float4) ----
    #pragma unroll
    for (int t = 0; t < 8; t++) {
        int idx = t * THREADS + tid;
        int row = idx >> 4;
        int cc  = (idx & 15) << 2;
        int kq  = s_ix[row];
        float4 q = *(const float4*)(g_embedT + kq * D + cc);
        float4 x = in4[idx];
        size_t o = (size_t)(n0 + row) * D + cc;
        *reinterpret_cast<float4*>(&q_out[o]) = q;
        if (diff_out) {
            float4 df;
            df.x = (q.x - x.x) * (q.x - x.x);
            df.y = (q.y - x.y) * (q.y - x.y);
            df.z = (q.z - x.z) * (q.z - x.z);
            df.w = (q.w - x.w) * (q.w - x.w);
            *reinterpret_cast<float4*>(&diff_out[o]) = df;
        }
    }
}

extern "C" void kernel_launch(void* const* d_in, const int* in_sizes, int n_in,
                              void* d_out, int out_size) {
    const float* input = (const float*)d_in[0];   // [B,T,D] fp32
    const float* embed = (const float*)d_in[1];   // [D,K]   fp32

    const int N = in_sizes[0] / D;
    const long nd = (long)N * D;

    float* out = (float*)d_out;
    float* q_out    = out;
    float* diff_out = nullptr;
    float* ind_out  = nullptr;
    if ((long)out_size >= 2 * nd + N) { diff_out = out + nd; ind_out = out + 2 * nd; }
    else if ((long)out_size >= 2 * nd) { diff_out = out + nd; }

    cudaFuncSetAttribute(vq_main, cudaFuncAttributeMaxDynamicSharedMemorySize, SMEM_TOTAL);

    vq_prep<<<(K * D + 255) / 256, 256>>>(embed);
    vq_main<<<N / BMT, THREADS, SMEM_TOTAL>>>(input, q_out, diff_out, ind_out);
}